// round 10
// baseline (speedup 1.0000x reference)
#include <cuda_runtime.h>
#include <cuda_fp16.h>
#include <math.h>

#define Mpts 100000
#define Bb 8
#define Kk 512
#define Nn 256
#define NROW 257              // Hermitian: rows 0..256 of pass-A output

#define BETA_F 13.85510032f   // pi*sqrt((J/ALPHA*(ALPHA-0.5))^2 - 0.8)
#define KSC 81.48733086f      // K/(2*pi)
#define PIJK 0.03681553891f   // pi*J/K

// fp16 grid: [cell][b], 8 complex-half per cell = 32B. 8 MB total.
__device__ __align__(16) __half2 g_gridh[Kk * Kk * Bb];
// pass-A output (Hermitian half): [b][k1(0..256)][c(0..255)]. 4.2 MB.
__device__ float2 g_grid2[Bb * NROW * Nn];
// real image after col-FFT + apod, TRANSPOSED: [b][c][r]. 2 MB.
__device__ float g_img[Bb * Nn * Nn];
__device__ int g_mm_i[2 * Bb];

// ---------------- helpers ----------------
__device__ __forceinline__ float2 cmul(float2 a, float2 b) {
    return make_float2(a.x * b.x - a.y * b.y, a.x * b.y + a.y * b.x);
}
__device__ __forceinline__ float2 cadd(float2 a, float2 b) { return make_float2(a.x + b.x, a.y + b.y); }
__device__ __forceinline__ float2 csub(float2 a, float2 b) { return make_float2(a.x - b.x, a.y - b.y); }

__device__ __forceinline__ int fenc(float v) {
    int b = __float_as_int(v);
    return b >= 0 ? b : (b ^ 0x7fffffff);
}

// Bessel I0 (A&S 9.8.1/9.8.2)
__device__ __forceinline__ float i0f(float x) {
    float ax = fabsf(x);
    if (ax < 3.75f) {
        float t = x / 3.75f;
        t *= t;
        return 1.0f + t * (3.5156229f + t * (3.0899424f + t * (1.2067492f +
               t * (0.2659732f + t * (0.0360768f + t * 0.0045813f)))));
    } else {
        float t = 3.75f / ax;
        float p = 0.39894228f + t * (0.01328592f + t * (0.00225319f +
                  t * (-0.00157565f + t * (0.00916281f + t * (-0.02057706f +
                  t * (0.02635537f + t * (-0.01647633f + t * 0.00392377f)))))));
        return (expf(ax) / sqrtf(ax)) * p;
    }
}

__device__ __forceinline__ float apodinv(int n) {
    float x = (float)(n - 128) * PIJK;
    float a = BETA_F * BETA_F - x * x;
    float sq = sqrtf(a);
    return sq / sinhf(sq);
}

// ---------------- zero grid + init minmax ----------------
__global__ void __launch_bounds__(256) zero_k() {
    int i = blockIdx.x * 256 + threadIdx.x;  // 524,288 float4 = 8 MB
    reinterpret_cast<float4*>(g_gridh)[i] = make_float4(0.f, 0.f, 0.f, 0.f);
    if (blockIdx.x == 0 && threadIdx.x < 2 * Bb)
        g_mm_i[threadIdx.x] = (threadIdx.x & 1) ? (int)0x80000000 : 0x7fffffff;
}

// ---------------- gridding scatter: 2 threads per point (R4-proven) --------
__global__ void __launch_bounds__(256) scatter_k(
    const float* __restrict__ yr, const float* __restrict__ yi,
    const float* __restrict__ wt, const float* __restrict__ uv) {
    int gid = blockIdx.x * 256 + threadIdx.x;
    int m = gid >> 1, q = gid & 1;   // q selects batches {4q..4q+3} (16B half-cell)
    if (m >= Mpts) return;

    float u = uv[2 * m], v = uv[2 * m + 1];
    float kfu = u * KSC, kfv = v * KSC;
    float fbu = floorf(kfu), fbv = floorf(kfv);
    int bu = (int)fbu, bv = (int)fbv;
    float fru = kfu - fbu, frv = kfv - fbv;

    float winv = 1.0f / i0f(BETA_F);

    float wu[6], wv[6];
    int iu[6], iv[6];
#pragma unroll
    for (int o = 0; o < 6; o++) {
        float du = (float)(o - 2) - fru;
        float dv = (float)(o - 2) - frv;
        float uu = du * (1.0f / 3.0f);
        float vv = dv * (1.0f / 3.0f);
        wu[o] = i0f(BETA_F * sqrtf(fmaxf(1.0f - uu * uu, 0.0f))) * winv;
        wv[o] = i0f(BETA_F * sqrtf(fmaxf(1.0f - vv * vv, 0.0f))) * winv;
        iu[o] = (bu + (o - 2) + Kk) & (Kk - 1);
        iv[o] = (bv + (o - 2) + Kk) & (Kk - 1);
    }

    float wm = wt[m];
    int b0 = 4 * q;
    float r0 = yr[(b0 + 0) * Mpts + m] * wm, i0v = yi[(b0 + 0) * Mpts + m] * wm;
    float r1 = yr[(b0 + 1) * Mpts + m] * wm, i1 = yi[(b0 + 1) * Mpts + m] * wm;
    float r2 = yr[(b0 + 2) * Mpts + m] * wm, i2 = yi[(b0 + 2) * Mpts + m] * wm;
    float r3 = yr[(b0 + 3) * Mpts + m] * wm, i3 = yi[(b0 + 3) * Mpts + m] * wm;

#pragma unroll
    for (int j1 = 0; j1 < 6; j1++) {
        int rb = iu[j1] << 9;
        float w1 = wu[j1];
#pragma unroll
        for (int j2 = 0; j2 < 6; j2++) {
            float ww = w1 * wv[j2];
            __half2 h0 = __floats2half2_rn(r0 * ww, i0v * ww);
            __half2 h1 = __floats2half2_rn(r1 * ww, i1 * ww);
            __half2 h2 = __floats2half2_rn(r2 * ww, i2 * ww);
            __half2 h3 = __floats2half2_rn(r3 * ww, i3 * ww);
            __half2* p = g_gridh + (((unsigned)(rb + iv[j2])) << 3) + (q << 2);
            asm volatile("red.global.add.noftz.v4.f16x2 [%0], {%1,%2,%3,%4};"
                         :: "l"(p),
                            "r"(*reinterpret_cast<unsigned*>(&h0)),
                            "r"(*reinterpret_cast<unsigned*>(&h1)),
                            "r"(*reinterpret_cast<unsigned*>(&h2)),
                            "r"(*reinterpret_cast<unsigned*>(&h3)) : "memory");
        }
    }
}

// ---------------- 512-pt inverse FFT, radix-8 Stockham (proven) -------------
#define PIDX(i) ((i) + ((i) >> 3))

__device__ __forceinline__ void fft8p(const float2* x, float2* y) {
    const float C = 0.70710678118654752f;
    float2 a0 = cadd(x[0], x[4]), a4 = csub(x[0], x[4]);
    float2 a1 = cadd(x[1], x[5]), t5 = csub(x[1], x[5]);
    float2 a2 = cadd(x[2], x[6]), t6 = csub(x[2], x[6]);
    float2 a3 = cadd(x[3], x[7]), t7 = csub(x[3], x[7]);
    float2 a5 = make_float2(C * (t5.x - t5.y), C * (t5.x + t5.y));
    float2 a6 = make_float2(-t6.y, t6.x);
    float2 a7 = make_float2(-C * (t7.x + t7.y), C * (t7.x - t7.y));

    float2 b0 = cadd(a0, a2), b2 = csub(a0, a2);
    float2 b1 = cadd(a1, a3), t3 = csub(a1, a3);
    float2 b3 = make_float2(-t3.y, t3.x);
    float2 b4 = cadd(a4, a6), b6 = csub(a4, a6);
    float2 b5 = cadd(a5, a7), u7 = csub(a5, a7);
    float2 b7 = make_float2(-u7.y, u7.x);

    y[0] = cadd(b0, b1); y[4] = csub(b0, b1);
    y[2] = cadd(b2, b3); y[6] = csub(b2, b3);
    y[1] = cadd(b4, b5); y[5] = csub(b4, b5);
    y[3] = cadd(b6, b7); y[7] = csub(b6, b7);
}

__device__ __forceinline__ void twiddle8(float2* x, float ang) {
    float2 w1; __sincosf(ang, &w1.y, &w1.x);
    float2 w = w1;
    x[1] = cmul(x[1], w);
#pragma unroll
    for (int i = 2; i < 8; i++) { w = cmul(w, w1); x[i] = cmul(x[i], w); }
}

__device__ __forceinline__ void fft512(float2* S, int t, float2* y) {
    float2 x[8];
#pragma unroll
    for (int i = 0; i < 8; i++) x[i] = S[PIDX(t + 64 * i)];
    fft8p(x, y);
    __syncthreads();
#pragma unroll
    for (int i = 0; i < 8; i++) S[PIDX(8 * t + i)] = y[i];
    __syncthreads();
#pragma unroll
    for (int i = 0; i < 8; i++) x[i] = S[PIDX(t + 64 * i)];
    {
        int k = t & 7;
        twiddle8(x, 0.09817477042f * (float)k);   // 2*pi/64
    }
    fft8p(x, y);
    __syncthreads();
    {
        int k = t & 7, g = t >> 3;
#pragma unroll
        for (int i = 0; i < 8; i++) S[PIDX(g * 64 + i * 8 + k)] = y[i];
    }
    __syncthreads();
#pragma unroll
    for (int i = 0; i < 8; i++) x[i] = S[PIDX(t + 64 * i)];
    twiddle8(x, 0.01227184630f * (float)t);       // 2*pi/512
    fft8p(x, y);
}

// ---------------- FFT pass A: Hermitian-projected rows 0..256 ---------------
// Gh[k1][k2] = 0.5*(G[k1][k2] + conj(G[-k1][-k2])). Then Re(ifft2(G)) =
// ifft2(Gh) and the pass-A output is Hermitian in k1 -> only rows 0..256 kept.
// grid = (257 rows, 2 batch-halves), 4 batches per 256-thread block.
__global__ void __launch_bounds__(256) fftA_k() {
    __shared__ float2 s[4 * 577];
    int k1 = blockIdx.x, q = blockIdx.y;
    const uint4* srcA = reinterpret_cast<const uint4*>(g_gridh + (size_t)k1 * (Kk * Bb));
    const uint4* srcB = reinterpret_cast<const uint4*>(g_gridh + (size_t)((Kk - k1) & (Kk - 1)) * (Kk * Bb));
    for (int k2 = threadIdx.x; k2 < Kk; k2 += 256) {
        uint4 a = srcA[k2 * 2 + q];
        uint4 bb = srcB[((Kk - k2) & (Kk - 1)) * 2 + q];
        const unsigned* ap = &a.x;
        const unsigned* bp = &bb.x;
#pragma unroll
        for (int l = 0; l < 4; l++) {
            float2 af = __half22float2(*reinterpret_cast<const __half2*>(&ap[l]));
            float2 bf = __half22float2(*reinterpret_cast<const __half2*>(&bp[l]));
            s[l * 577 + PIDX(k2)] = make_float2(0.5f * (af.x + bf.x), 0.5f * (af.y - bf.y));
        }
    }
    __syncthreads();

    int bl = threadIdx.x >> 6, t = threadIdx.x & 63;
    int b = q * 4 + bl;
    float2 y[8];
    fft512(s + bl * 577, t, y);

    float2* dst = g_grid2 + ((size_t)b * NROW + k1) * Nn;
#pragma unroll
    for (int i = 0; i < 8; i++) {
        int n = i * 64 + t;
        int c = (n < 128) ? (n + 128) : (n - 384);
        if (n < 128 || n >= 384) dst[c] = y[i];
    }
}

// ---------------- 256-pt inverse FFT, radix-4 Stockham, 64 threads ----------
#define S4IDX(i) ((i) + ((i) >> 2))

__device__ __forceinline__ void fft4p(const float2* x, float2* y) {
    float2 a = cadd(x[0], x[2]), bq = csub(x[0], x[2]);
    float2 c = cadd(x[1], x[3]), d = csub(x[1], x[3]);
    float2 id = make_float2(-d.y, d.x);     // +i*d (inverse)
    y[0] = cadd(a, c);
    y[1] = cadd(bq, id);
    y[2] = csub(a, c);
    y[3] = csub(bq, id);
}

__device__ __forceinline__ void twiddle4(float2* x, float ang) {
    float2 w1; __sincosf(ang, &w1.y, &w1.x);
    float2 w2 = cmul(w1, w1);
    x[1] = cmul(x[1], w1);
    x[2] = cmul(x[2], w2);
    x[3] = cmul(x[3], cmul(w2, w1));
}

__device__ __forceinline__ void fft256(float2* S, int t, float2* y) {
    float2 x[4];
    // stage 0 (L=1)
#pragma unroll
    for (int i = 0; i < 4; i++) x[i] = S[S4IDX(t + 64 * i)];
    fft4p(x, y);
    __syncthreads();
#pragma unroll
    for (int i = 0; i < 4; i++) S[S4IDX(4 * t + i)] = y[i];
    __syncthreads();
    // stage 1 (L=4)
#pragma unroll
    for (int i = 0; i < 4; i++) x[i] = S[S4IDX(t + 64 * i)];
    {
        int k = t & 3;
        twiddle4(x, 0.39269908169872415f * (float)k);   // 2*pi/16
        fft4p(x, y);
        __syncthreads();
        int g = t >> 2;
#pragma unroll
        for (int i = 0; i < 4; i++) S[S4IDX(g * 16 + i * 4 + k)] = y[i];
    }
    __syncthreads();
    // stage 2 (L=16)
#pragma unroll
    for (int i = 0; i < 4; i++) x[i] = S[S4IDX(t + 64 * i)];
    {
        int k = t & 15;
        twiddle4(x, 0.09817477042468103f * (float)k);   // 2*pi/64
        fft4p(x, y);
        __syncthreads();
        int g = t >> 4;
#pragma unroll
        for (int i = 0; i < 4; i++) S[S4IDX(g * 64 + i * 16 + k)] = y[i];
    }
    __syncthreads();
    // stage 3 (L=64) — outputs stay in registers, bins n = i*64 + t
#pragma unroll
    for (int i = 0; i < 4; i++) x[i] = S[S4IDX(t + 64 * i)];
    twiddle4(x, 0.024543692606170259f * (float)t);      // 2*pi/256
    fft4p(x, y);
}

// ---------------- FFT pass B: 512-pt C2R via 256-pt complex FFT -------------
// H[k], k=0..256 is the Hermitian half of the column. Even/odd repack:
//   P[k] = G[k] + G[k+256],  Q[k] = (G[k] - G[k+256]) * e^{+2pi i k/512}
//   Z[k] = P[k] + i*Q[k];  z = IDFT_256(Z);  x[2m]=Re z[m], x[2m+1]=Im z[m].
__global__ void __launch_bounds__(64) fftB_k() {
    __shared__ float2 Hs[NROW];
    __shared__ float2 S[340];
    __shared__ float swn[2], swx[2];
    int bj = blockIdx.x;            // b*256 + c
    int b = bj >> 8, c = bj & 255;
    const float2* src = g_grid2 + (size_t)b * (NROW * Nn) + c;
    int t = threadIdx.x;
    for (int k = t; k < NROW; k += 64) Hs[k] = src[(size_t)k * Nn];
    __syncthreads();

#pragma unroll
    for (int i = 0; i < 4; i++) {
        int k = t + 64 * i;
        float2 Gk = Hs[k];
        float2 G2;
        if (k == 0) G2 = Hs[256];
        else { float2 h = Hs[256 - k]; G2 = make_float2(h.x, -h.y); }
        float2 P = cadd(Gk, G2);
        float2 Qr = csub(Gk, G2);
        float sn, cs;
        __sincosf(0.01227184630308513f * (float)k, &sn, &cs);  // 2*pi/512
        float2 Q = make_float2(Qr.x * cs - Qr.y * sn, Qr.x * sn + Qr.y * cs);
        S[S4IDX(k)] = make_float2(P.x - Q.y, P.y + Q.x);
    }
    __syncthreads();

    float2 y[4];
    fft256(S, t, y);

    // y[0]: m=t     -> x[2t], x[2t+1]     -> jr = 2t+128, 2t+129
    // y[3]: m=192+t -> x[384+2t],x[385+2t]-> jr = 2t,     2t+1
    float ac = apodinv(c);
    float* dst = g_img + ((size_t)b * Nn + c) * Nn;   // [b][c][r]
    float v0 = y[3].x * apodinv(2 * t) * ac;
    float v1 = y[3].y * apodinv(2 * t + 1) * ac;
    float v2 = y[0].x * apodinv(2 * t + 128) * ac;
    float v3 = y[0].y * apodinv(2 * t + 129) * ac;
    *reinterpret_cast<float2*>(dst + 2 * t) = make_float2(v0, v1);
    *reinterpret_cast<float2*>(dst + 2 * t + 128) = make_float2(v2, v3);

    float mn = fminf(fminf(v0, v1), fminf(v2, v3));
    float mx = fmaxf(fmaxf(v0, v1), fmaxf(v2, v3));
#pragma unroll
    for (int off = 16; off; off >>= 1) {
        mn = fminf(mn, __shfl_xor_sync(0xffffffffu, mn, off));
        mx = fmaxf(mx, __shfl_xor_sync(0xffffffffu, mx, off));
    }
    int w = t >> 5;
    if ((t & 31) == 0) { swn[w] = mn; swx[w] = mx; }
    __syncthreads();
    if (t == 0) {
        mn = fminf(mn, swn[1]); mx = fmaxf(mx, swx[1]);
        atomicMin(&g_mm_i[2 * b], fenc(mn));
        atomicMax(&g_mm_i[2 * b + 1], fenc(mx));
    }
}

// ---------------- normalize + transpose [b][c][r] -> out [b][r][c] ----------
__global__ void __launch_bounds__(256) norm_k(float* __restrict__ out) {
    __shared__ float tile[32][33];
    int b = blockIdx.z;
    int c0 = blockIdx.x * 32, r0 = blockIdx.y * 32;
    int tx = threadIdx.x & 31, ty = threadIdx.x >> 5;

    int emn = g_mm_i[2 * b], emx = g_mm_i[2 * b + 1];
    float mn = __int_as_float(emn < 0 ? (emn ^ 0x7fffffff) : emn);
    float mx = __int_as_float(emx < 0 ? (emx ^ 0x7fffffff) : emx);
    float inv = 1.0f / (mx - mn);

    const float* src = g_img + ((size_t)b << 16);
    float* dst = out + ((size_t)b << 16);
#pragma unroll
    for (int yy = ty; yy < 32; yy += 8)
        tile[yy][tx] = src[(c0 + yy) * Nn + r0 + tx];
    __syncthreads();
#pragma unroll
    for (int yy = ty; yy < 32; yy += 8)
        dst[(r0 + yy) * Nn + c0 + tx] = (tile[tx][yy] - mn) * inv;
}

extern "C" void kernel_launch(void* const* d_in, const int* in_sizes, int n_in,
                              void* d_out, int out_size) {
    const float* yr = (const float*)d_in[0];
    const float* yi = (const float*)d_in[1];
    const float* wt = (const float*)d_in[2];
    const float* uv = (const float*)d_in[3];
    float* out = (float*)d_out;

    zero_k<<<2048, 256>>>();
    scatter_k<<<(2 * Mpts + 255) / 256, 256>>>(yr, yi, wt, uv);
    fftA_k<<<dim3(NROW, 2), 256>>>();
    fftB_k<<<Bb * Nn, 64>>>();
    norm_k<<<dim3(8, 8, 8), 256>>>(out);
}